// round 1
// baseline (speedup 1.0000x reference)
#include <cuda_runtime.h>
#include <cuda_fp16.h>
#include <stdint.h>

#define NB   8
#define NC   256
#define NPIX 4096
#define KST  768      // stacked K: [x_h; x_l; x_h]
#define MR   320      // 32 q + 32 k + 256 v output channels

// ---------------- scratch (device globals; no allocation) ----------------
__device__ __half g_xs[(size_t)NB * KST * NPIX];   // 50.3 MB stacked x (fp16 hi/lo)
__device__ __half g_ws[MR * KST];                  // stacked weights
__device__ __half g_qT[(size_t)NB * NPIX * 32];    // [b][n][d]
__device__ __half g_kT[(size_t)NB * NPIX * 32];    // [b][n][d]
__device__ __half g_vT[(size_t)NB * NPIX * NC];    // [b][n][c]

// ---------------- mma / ldmatrix helpers ----------------
__device__ __forceinline__ unsigned smem_u32(const void* p) {
    return (unsigned)__cvta_generic_to_shared(p);
}
__device__ __forceinline__ void ldm_x4(uint32_t* r, unsigned addr) {
    asm volatile("ldmatrix.sync.aligned.m8n8.x4.shared.b16 {%0,%1,%2,%3}, [%4];\n"
                 : "=r"(r[0]), "=r"(r[1]), "=r"(r[2]), "=r"(r[3]) : "r"(addr));
}
__device__ __forceinline__ void ldm_x4_t(uint32_t* r, unsigned addr) {
    asm volatile("ldmatrix.sync.aligned.m8n8.x4.trans.shared.b16 {%0,%1,%2,%3}, [%4];\n"
                 : "=r"(r[0]), "=r"(r[1]), "=r"(r[2]), "=r"(r[3]) : "r"(addr));
}
__device__ __forceinline__ void mma_16816(float* d, const uint32_t* a, uint32_t b0, uint32_t b1) {
    asm volatile(
        "mma.sync.aligned.m16n8k16.row.col.f32.f16.f16.f32 "
        "{%0,%1,%2,%3},{%4,%5,%6,%7},{%8,%9},{%0,%1,%2,%3};\n"
        : "+f"(d[0]), "+f"(d[1]), "+f"(d[2]), "+f"(d[3])
        : "r"(a[0]), "r"(a[1]), "r"(a[2]), "r"(a[3]), "r"(b0), "r"(b1));
}

// ---------------- pack kernels ----------------
__global__ void pack_w_kernel(const float* __restrict__ wq, const float* __restrict__ wk,
                              const float* __restrict__ wv) {
    int idx = blockIdx.x * blockDim.x + threadIdx.x;
    if (idx >= MR * NC) return;
    int k = idx & 255;
    int m = idx >> 8;
    float w = (m < 32) ? wq[m * NC + k] : (m < 64) ? wk[(m - 32) * NC + k] : wv[(m - 64) * NC + k];
    __half hi = __float2half_rn(w);
    __half lo = __float2half_rn(w - __half2float(hi));
    g_ws[m * KST + k]       = hi;   // pairs with x_h
    g_ws[m * KST + 256 + k] = hi;   // pairs with x_l
    g_ws[m * KST + 512 + k] = lo;   // pairs with x_h
}

__global__ void pack_x_kernel(const float* __restrict__ x) {
    int idx = blockIdx.x * blockDim.x + threadIdx.x;  // one float4 each
    const int total = NB * NC * NPIX / 4;
    if (idx >= total) return;
    float4 v = ((const float4*)x)[idx];
    int n4 = idx % (NPIX / 4);
    int t  = idx / (NPIX / 4);
    int c  = t % NC;
    int b  = t / NC;
    float f[4] = {v.x, v.y, v.z, v.w};
    __align__(8) __half hi[4], lo[4];
#pragma unroll
    for (int i = 0; i < 4; i++) {
        hi[i] = __float2half_rn(f[i]);
        lo[i] = __float2half_rn(f[i] - __half2float(hi[i]));
    }
    size_t base = ((size_t)b * KST) * NPIX + (size_t)n4 * 4;
    *(uint2*)&g_xs[base + (size_t)c * NPIX]         = *(uint2*)&hi[0];
    *(uint2*)&g_xs[base + (size_t)(c + 256) * NPIX] = *(uint2*)&lo[0];
    *(uint2*)&g_xs[base + (size_t)(c + 512) * NPIX] = *(uint2*)&hi[0];
}

// ---------------- projection GEMM: C[320,4096] = Ws[320,768] * Xs[768,4096] ----------------
#define PA_STR 40
#define PB_STR 72

__global__ __launch_bounds__(128) void proj_kernel(const float* __restrict__ bq,
                                                   const float* __restrict__ bk,
                                                   const float* __restrict__ bv) {
    __shared__ __half a_s[64 * PA_STR];
    __shared__ __half b_s[32 * PB_STR];
    __shared__ __half c_s[64 * PB_STR];

    int n0 = blockIdx.x * 64;
    int m0 = blockIdx.y * 64;
    int b  = blockIdx.z;
    int tid = threadIdx.x;
    int w = tid >> 5, lane = tid & 31;
    int g = lane >> 2, t4 = lane & 3;

    float acc[8][4];
#pragma unroll
    for (int i = 0; i < 8; i++)
#pragma unroll
        for (int j = 0; j < 4; j++) acc[i][j] = 0.f;

    const __half* gA = &g_ws[m0 * KST];
    const __half* gB = &g_xs[(size_t)b * KST * NPIX + n0];

    for (int kt = 0; kt < KST / 32; kt++) {
        int k0 = kt * 32;
        __syncthreads();
#pragma unroll
        for (int p = 0; p < 2; p++) {  // A: 64x32
            int e = (tid + p * 128) * 8;
            int r = e >> 5, c = e & 31;
            *(uint4*)&a_s[r * PA_STR + c] = *(const uint4*)&gA[r * KST + k0 + c];
        }
#pragma unroll
        for (int p = 0; p < 2; p++) {  // B: 32x64
            int e = (tid + p * 128) * 8;
            int r = e >> 6, c = e & 63;
            *(uint4*)&b_s[r * PB_STR + c] = *(const uint4*)&gB[(size_t)(k0 + r) * NPIX + c];
        }
        __syncthreads();
#pragma unroll
        for (int ks = 0; ks < 2; ks++) {
            uint32_t af[4];
            {
                int row = 16 * w + (lane & 15);
                int col = 16 * ks + ((lane >= 16) ? 8 : 0);
                ldm_x4(af, smem_u32(&a_s[row * PA_STR + col]));
            }
#pragma unroll
            for (int nbp = 0; nbp < 4; nbp++) {
                uint32_t bf[4];
                int row = 16 * ks + (lane & 15);
                int col = 16 * nbp + ((lane >= 16) ? 8 : 0);
                ldm_x4_t(bf, smem_u32(&b_s[row * PB_STR + col]));
                mma_16816(acc[2 * nbp],     af, bf[0], bf[1]);
                mma_16816(acc[2 * nbp + 1], af, bf[2], bf[3]);
            }
        }
    }
    __syncthreads();
    // bias + fp16 stage
    int row_a = 16 * w + g;
    int row_b = row_a + 8;
    int ma = m0 + row_a, mb = m0 + row_b;
    float bias_a = (ma < 32) ? bq[ma] : (ma < 64) ? bk[ma - 32] : bv[ma - 64];
    float bias_b = (mb < 32) ? bq[mb] : (mb < 64) ? bk[mb - 32] : bv[mb - 64];
#pragma unroll
    for (int nt = 0; nt < 8; nt++) {
        int col = 8 * nt + 2 * t4;
        c_s[row_a * PB_STR + col]     = __float2half_rn(acc[nt][0] + bias_a);
        c_s[row_a * PB_STR + col + 1] = __float2half_rn(acc[nt][1] + bias_a);
        c_s[row_b * PB_STR + col]     = __float2half_rn(acc[nt][2] + bias_b);
        c_s[row_b * PB_STR + col + 1] = __float2half_rn(acc[nt][3] + bias_b);
    }
    __syncthreads();
    // transposed coalesced writeback
    int n = tid & 63, part = tid >> 6;
    __align__(16) __half tmp[32];
#pragma unroll
    for (int j = 0; j < 32; j++) tmp[j] = c_s[(part * 32 + j) * PB_STR + n];
    int ng = n0 + n;
    __half* dst;
    if (m0 == 0) {
        dst = (part == 0) ? &g_qT[((size_t)b * NPIX + ng) * 32]
                          : &g_kT[((size_t)b * NPIX + ng) * 32];
    } else {
        int cb = (m0 - 64) + part * 32;
        dst = &g_vT[((size_t)b * NPIX + ng) * NC + cb];
    }
#pragma unroll
    for (int q = 0; q < 4; q++) ((uint4*)dst)[q] = ((uint4*)tmp)[q];
}

// ---------------- flash attention ----------------
// smem byte offsets
#define OFF_Q 0        // [64][40] half  = 5120
#define OFF_K 5120     // [64][40] half  = 5120
#define OFF_V 10240    // [64][264] half = 33792
#define OFF_S 44032    // [64][66] float = 16896
#define OFF_P 60928    // [64][72] half  = 9216
#define OFF_M 70144    // [64] float
#define OFF_L 70400    // [64] float
#define OFF_A 70656    // [64] float
#define SMEM_TOTAL 70912
#define VSTR 264
#define SSTR 66
#define PSTR 72

__global__ __launch_bounds__(256) void flash_kernel(float* __restrict__ out) {
    extern __shared__ char smem_raw[];
    __half* q_s = (__half*)(smem_raw + OFF_Q);
    __half* k_s = (__half*)(smem_raw + OFF_K);
    __half* v_s = (__half*)(smem_raw + OFF_V);
    float*  S_s = (float*)(smem_raw + OFF_S);
    __half* P_s = (__half*)(smem_raw + OFF_P);
    float*  m_s = (float*)(smem_raw + OFF_M);
    float*  l_s = (float*)(smem_raw + OFF_L);
    float*  al_s = (float*)(smem_raw + OFF_A);

    int nq0 = blockIdx.x * 64;
    int b   = blockIdx.y;
    int tid = threadIdx.x;
    int w = tid >> 5, lane = tid & 31, g = lane >> 2, t4 = lane & 3;
    int mw = w & 3, nh = w >> 2;

    {   // load Q tile (64x32)
        int e = tid * 8;
        int r = e >> 5, c = e & 31;
        *(uint4*)&q_s[r * 40 + c] = *(const uint4*)&g_qT[((size_t)b * NPIX + nq0 + r) * 32 + c];
    }
    if (tid < 64) { m_s[tid] = -1e30f; l_s[tid] = 0.f; }
    float acc[16][4];
#pragma unroll
    for (int i = 0; i < 16; i++)
#pragma unroll
        for (int j = 0; j < 4; j++) acc[i][j] = 0.f;
    __syncthreads();

    // Q fragments (constant across key chunks)
    uint32_t qa[2][4];
#pragma unroll
    for (int ks = 0; ks < 2; ks++) {
        int row = 16 * mw + (lane & 15);
        int col = 16 * ks + ((lane >= 16) ? 8 : 0);
        ldm_x4(qa[ks], smem_u32(&q_s[row * 40 + col]));
    }

    for (int kc = 0; kc < NPIX / 64; kc++) {
        int j0 = kc * 64;
        __syncthreads();  // protect k_s/v_s/P_s from previous iteration readers
        {   // K chunk 64x32
            int e = tid * 8;
            int r = e >> 5, c = e & 31;
            *(uint4*)&k_s[r * 40 + c] = *(const uint4*)&g_kT[((size_t)b * NPIX + j0 + r) * 32 + c];
        }
#pragma unroll
        for (int p = 0; p < 8; p++) {  // V chunk 64x256
            int e = (tid + p * 256) * 8;
            int r = e >> 8, c = e & 255;
            *(uint4*)&v_s[r * VSTR + c] = *(const uint4*)&g_vT[((size_t)b * NPIX + j0 + r) * NC + c];
        }
        __syncthreads();

        // S = Q K^T : warp covers rows [16*mw,+16), keys [32*nh,+32)
        float sacc[4][4];
#pragma unroll
        for (int i = 0; i < 4; i++)
#pragma unroll
            for (int j = 0; j < 4; j++) sacc[i][j] = 0.f;
#pragma unroll
        for (int ks = 0; ks < 2; ks++) {
#pragma unroll
            for (int nbp = 0; nbp < 2; nbp++) {
                uint32_t bf[4];
                int key = nh * 32 + nbp * 16 + (lane & 7) + ((lane >= 16) ? 8 : 0);
                int col = 16 * ks + ((lane & 8) ? 8 : 0);
                ldm_x4(bf, smem_u32(&k_s[key * 40 + col]));
                mma_16816(sacc[2 * nbp],     qa[ks], bf[0], bf[1]);
                mma_16816(sacc[2 * nbp + 1], qa[ks], bf[2], bf[3]);
            }
        }
        {   // dump S to smem
            int ra = 16 * mw + g;
#pragma unroll
            for (int nb = 0; nb < 4; nb++) {
                int col = nh * 32 + 8 * nb + 2 * t4;
                S_s[ra * SSTR + col]           = sacc[nb][0];
                S_s[ra * SSTR + col + 1]       = sacc[nb][1];
                S_s[(ra + 8) * SSTR + col]     = sacc[nb][2];
                S_s[(ra + 8) * SSTR + col + 1] = sacc[nb][3];
            }
        }
        __syncthreads();

        // online softmax: warp w owns rows [8w, 8w+8)
#pragma unroll
        for (int rr = 0; rr < 8; rr++) {
            int r = 8 * w + rr;
            float s0 = S_s[r * SSTR + 2 * lane];
            float s1 = S_s[r * SSTR + 2 * lane + 1];
            float mx = fmaxf(s0, s1);
#pragma unroll
            for (int off = 16; off; off >>= 1) mx = fmaxf(mx, __shfl_xor_sync(0xffffffffu, mx, off));
            float m_old = m_s[r];
            float m_new = fmaxf(m_old, mx);
            float p0 = __expf(s0 - m_new);
            float p1 = __expf(s1 - m_new);
            float sum = p0 + p1;
#pragma unroll
            for (int off = 16; off; off >>= 1) sum += __shfl_xor_sync(0xffffffffu, sum, off);
            float alpha = __expf(m_old - m_new);
            if (lane == 0) {
                m_s[r]  = m_new;
                l_s[r]  = l_s[r] * alpha + sum;
                al_s[r] = alpha;
            }
            *(__half2*)&P_s[r * PSTR + 2 * lane] = __floats2half2_rn(p0, p1);
        }
        __syncthreads();

        // rescale O accumulators
        {
            int ra = 16 * mw + g;
            float aa = al_s[ra], ab = al_s[ra + 8];
#pragma unroll
            for (int nt = 0; nt < 16; nt++) {
                acc[nt][0] *= aa; acc[nt][1] *= aa;
                acc[nt][2] *= ab; acc[nt][3] *= ab;
            }
        }
        // O += P V : warp covers rows [16*mw,+16), chans [128*nh,+128)
#pragma unroll
        for (int ks = 0; ks < 4; ks++) {
            uint32_t pa[4];
            {
                int row = 16 * mw + (lane & 15);
                int col = 16 * ks + ((lane >= 16) ? 8 : 0);
                ldm_x4(pa, smem_u32(&P_s[row * PSTR + col]));
            }
#pragma unroll
            for (int nbp = 0; nbp < 8; nbp++) {
                uint32_t bf[4];
                int key  = 16 * ks + (lane & 15);
                int chan = nh * 128 + 16 * nbp + ((lane >= 16) ? 8 : 0);
                ldm_x4_t(bf, smem_u32(&v_s[key * VSTR + chan]));
                mma_16816(acc[2 * nbp],     pa, bf[0], bf[1]);
                mma_16816(acc[2 * nbp + 1], pa, bf[2], bf[3]);
            }
        }
    }
    __syncthreads();

    // finalize: divide by l, stage transposed, coalesced write
    float* o_s = (float*)smem_raw;  // [64][260], 66560B — reuses everything
    {
        int ra = 16 * mw + g;
        float inv_a = 1.f / l_s[ra];
        float inv_b = 1.f / l_s[ra + 8];
        __syncthreads();  // everyone read l_s before overwrite
#pragma unroll
        for (int nt = 0; nt < 16; nt++) {
            int col = nh * 128 + 8 * nt + 2 * t4;
            o_s[ra * 260 + col]           = acc[nt][0] * inv_a;
            o_s[ra * 260 + col + 1]       = acc[nt][1] * inv_a;
            o_s[(ra + 8) * 260 + col]     = acc[nt][2] * inv_b;
            o_s[(ra + 8) * 260 + col + 1] = acc[nt][3] * inv_b;
        }
    }
    __syncthreads();
    int nl = tid & 63;
    int cb = tid >> 6;  // 0..3
#pragma unroll
    for (int it = 0; it < 64; it++) {
        int c = it * 4 + cb;
        out[((size_t)b * NC + c) * NPIX + nq0 + nl] = o_s[nl * 260 + c];
    }
}

// ---------------- launcher ----------------
extern "C" void kernel_launch(void* const* d_in, const int* in_sizes, int n_in,
                              void* d_out, int out_size) {
    (void)in_sizes; (void)n_in; (void)out_size;
    const float* x  = (const float*)d_in[0];
    const float* wq = (const float*)d_in[1];
    const float* bq = (const float*)d_in[2];
    const float* wk = (const float*)d_in[3];
    const float* bk = (const float*)d_in[4];
    const float* wv = (const float*)d_in[5];
    const float* bv = (const float*)d_in[6];
    float* out = (float*)d_out;

    pack_w_kernel<<<(MR * NC + 255) / 256, 256>>>(wq, wk, wv);
    pack_x_kernel<<<(NB * NC * NPIX / 4 + 255) / 256, 256>>>(x);

    dim3 pg(NPIX / 64, MR / 64, NB);
    proj_kernel<<<pg, 128>>>(bq, bk, bv);

    cudaFuncSetAttribute(flash_kernel, cudaFuncAttributeMaxDynamicSharedMemorySize, SMEM_TOTAL);
    dim3 fg(NPIX / 64, NB);
    flash_kernel<<<fg, 256, SMEM_TOTAL>>>(out);
}

// round 3
// speedup vs baseline: 2.1334x; 2.1334x over previous
#include <cuda_runtime.h>
#include <cuda_fp16.h>
#include <stdint.h>

#define NB   8
#define NC   256
#define NPIX 4096
#define KST  768      // stacked K: [x_h; x_l; x_h(reused)]
#define KSL  512      // stored slabs (hi, lo)
#define MR   320      // 32 q + 32 k + 256 v output channels

// ---------------- scratch (device globals; no allocation) ----------------
__device__ __half g_xs[(size_t)NB * KSL * NPIX];   // 33.5 MB stacked x (fp16 hi/lo)
__device__ __half g_ws[MR * KST];                  // stacked weights
__device__ __half g_qT[(size_t)NB * NPIX * 32];    // [b][n][d]
__device__ __half g_kT[(size_t)NB * NPIX * 32];    // [b][n][d]
__device__ __half g_vT[(size_t)NB * NPIX * NC];    // [b][n][c]

// ---------------- mma / ldmatrix / cp.async helpers ----------------
__device__ __forceinline__ unsigned smem_u32(const void* p) {
    return (unsigned)__cvta_generic_to_shared(p);
}
__device__ __forceinline__ uint32_t h2_as_u32(__half2 h) {
    return *reinterpret_cast<uint32_t*>(&h);
}
__device__ __forceinline__ void ldm_x4(uint32_t* r, unsigned addr) {
    asm volatile("ldmatrix.sync.aligned.m8n8.x4.shared.b16 {%0,%1,%2,%3}, [%4];\n"
                 : "=r"(r[0]), "=r"(r[1]), "=r"(r[2]), "=r"(r[3]) : "r"(addr));
}
__device__ __forceinline__ void ldm_x4_t(uint32_t* r, unsigned addr) {
    asm volatile("ldmatrix.sync.aligned.m8n8.x4.trans.shared.b16 {%0,%1,%2,%3}, [%4];\n"
                 : "=r"(r[0]), "=r"(r[1]), "=r"(r[2]), "=r"(r[3]) : "r"(addr));
}
__device__ __forceinline__ void mma_16816(float* d, const uint32_t* a, uint32_t b0, uint32_t b1) {
    asm volatile(
        "mma.sync.aligned.m16n8k16.row.col.f32.f16.f16.f32 "
        "{%0,%1,%2,%3},{%4,%5,%6,%7},{%8,%9},{%0,%1,%2,%3};\n"
        : "+f"(d[0]), "+f"(d[1]), "+f"(d[2]), "+f"(d[3])
        : "r"(a[0]), "r"(a[1]), "r"(a[2]), "r"(a[3]), "r"(b0), "r"(b1));
}
__device__ __forceinline__ void cp_async16(unsigned dst, const void* src) {
    asm volatile("cp.async.cg.shared.global [%0], [%1], 16;\n" :: "r"(dst), "l"(src));
}
__device__ __forceinline__ void cp_commit() {
    asm volatile("cp.async.commit_group;\n");
}
template <int N>
__device__ __forceinline__ void cp_wait() {
    asm volatile("cp.async.wait_group %0;\n" :: "n"(N));
}

// ---------------- pack kernels ----------------
__global__ void pack_w_kernel(const float* __restrict__ wq, const float* __restrict__ wk,
                              const float* __restrict__ wv) {
    int idx = blockIdx.x * blockDim.x + threadIdx.x;
    if (idx >= MR * NC) return;
    int k = idx & 255;
    int m = idx >> 8;
    float w = (m < 32) ? wq[m * NC + k] : (m < 64) ? wk[(m - 32) * NC + k] : wv[(m - 64) * NC + k];
    __half hi = __float2half_rn(w);
    __half lo = __float2half_rn(w - __half2float(hi));
    g_ws[m * KST + k]       = hi;   // pairs with x_h
    g_ws[m * KST + 256 + k] = hi;   // pairs with x_l
    g_ws[m * KST + 512 + k] = lo;   // pairs with x_h (re-read slab 0)
}

__global__ void pack_x_kernel(const float* __restrict__ x) {
    int idx = blockIdx.x * blockDim.x + threadIdx.x;  // one float4 each
    const int total = NB * NC * NPIX / 4;
    if (idx >= total) return;
    float4 v = ((const float4*)x)[idx];
    int n4 = idx % (NPIX / 4);
    int t  = idx / (NPIX / 4);
    int c  = t % NC;
    int b  = t / NC;
    float f[4] = {v.x, v.y, v.z, v.w};
    __align__(8) __half hi[4], lo[4];
#pragma unroll
    for (int i = 0; i < 4; i++) {
        hi[i] = __float2half_rn(f[i]);
        lo[i] = __float2half_rn(f[i] - __half2float(hi[i]));
    }
    size_t base = ((size_t)b * KSL) * NPIX + (size_t)n4 * 4;
    *(uint2*)&g_xs[base + (size_t)c * NPIX]         = *(uint2*)&hi[0];
    *(uint2*)&g_xs[base + (size_t)(c + 256) * NPIX] = *(uint2*)&lo[0];
}

// ---------------- projection GEMM: C[320,4096] = Ws[320,768] * Xs[768,4096] ----------------
#define PA_STR 40
#define PB_STR 72

__global__ __launch_bounds__(128) void proj_kernel(const float* __restrict__ bq,
                                                   const float* __restrict__ bk,
                                                   const float* __restrict__ bv) {
    __shared__ __half a_s[64 * PA_STR];
    __shared__ __half b_s[32 * PB_STR];
    __shared__ __half c_s[64 * PB_STR];

    int n0 = blockIdx.x * 64;
    int m0 = blockIdx.y * 64;
    int b  = blockIdx.z;
    int tid = threadIdx.x;
    int w = tid >> 5, lane = tid & 31;
    int g = lane >> 2, t4 = lane & 3;

    float acc[8][4];
#pragma unroll
    for (int i = 0; i < 8; i++)
#pragma unroll
        for (int j = 0; j < 4; j++) acc[i][j] = 0.f;

    const __half* gA = &g_ws[m0 * KST];
    const __half* gB = &g_xs[(size_t)b * KSL * NPIX + n0];

    for (int kt = 0; kt < KST / 32; kt++) {
        int k0 = kt * 32;
        int kk = (k0 < KSL) ? k0 : (k0 - KSL);  // hi slab re-read for lo-weight rows
        __syncthreads();
#pragma unroll
        for (int p = 0; p < 2; p++) {  // A: 64x32
            int e = (tid + p * 128) * 8;
            int r = e >> 5, c = e & 31;
            *(uint4*)&a_s[r * PA_STR + c] = *(const uint4*)&gA[r * KST + k0 + c];
        }
#pragma unroll
        for (int p = 0; p < 2; p++) {  // B: 32x64
            int e = (tid + p * 128) * 8;
            int r = e >> 6, c = e & 63;
            *(uint4*)&b_s[r * PB_STR + c] = *(const uint4*)&gB[(size_t)(kk + r) * NPIX + c];
        }
        __syncthreads();
#pragma unroll
        for (int ks = 0; ks < 2; ks++) {
            uint32_t af[4];
            {
                int row = 16 * w + (lane & 15);
                int col = 16 * ks + ((lane >= 16) ? 8 : 0);
                ldm_x4(af, smem_u32(&a_s[row * PA_STR + col]));
            }
#pragma unroll
            for (int nbp = 0; nbp < 4; nbp++) {
                uint32_t bf[4];
                int row = 16 * ks + (lane & 15);
                int col = 16 * nbp + ((lane >= 16) ? 8 : 0);
                ldm_x4_t(bf, smem_u32(&b_s[row * PB_STR + col]));
                mma_16816(acc[2 * nbp],     af, bf[0], bf[1]);
                mma_16816(acc[2 * nbp + 1], af, bf[2], bf[3]);
            }
        }
    }
    __syncthreads();
    // bias + fp16 stage
    int row_a = 16 * w + g;
    int row_b = row_a + 8;
    int ma = m0 + row_a, mb = m0 + row_b;
    float bias_a = (ma < 32) ? bq[ma] : (ma < 64) ? bk[ma - 32] : bv[ma - 64];
    float bias_b = (mb < 32) ? bq[mb] : (mb < 64) ? bk[mb - 32] : bv[mb - 64];
#pragma unroll
    for (int nt = 0; nt < 8; nt++) {
        int col = 8 * nt + 2 * t4;
        c_s[row_a * PB_STR + col]     = __float2half_rn(acc[nt][0] + bias_a);
        c_s[row_a * PB_STR + col + 1] = __float2half_rn(acc[nt][1] + bias_a);
        c_s[row_b * PB_STR + col]     = __float2half_rn(acc[nt][2] + bias_b);
        c_s[row_b * PB_STR + col + 1] = __float2half_rn(acc[nt][3] + bias_b);
    }
    __syncthreads();
    // transposed coalesced writeback
    int n = tid & 63, part = tid >> 6;
    __align__(16) __half tmp[32];
#pragma unroll
    for (int j = 0; j < 32; j++) tmp[j] = c_s[(part * 32 + j) * PB_STR + n];
    int ng = n0 + n;
    __half* dst;
    if (m0 == 0) {
        dst = (part == 0) ? &g_qT[((size_t)b * NPIX + ng) * 32]
                          : &g_kT[((size_t)b * NPIX + ng) * 32];
    } else {
        int cb = (m0 - 64) + part * 32;
        dst = &g_vT[((size_t)b * NPIX + ng) * NC + cb];
    }
#pragma unroll
    for (int q = 0; q < 4; q++) ((uint4*)dst)[q] = ((uint4*)tmp)[q];
}

// ---------------- flash attention (register softmax + cp.async pipeline) ----------------
#define VSTR 264
#define KTILE_B (64 * 40 * 2)          // 5120
#define VTILE_B (64 * VSTR * 2)        // 33792
#define OFF_Q 0
#define OFF_K 5120                     // 2 buffers
#define OFF_V (5120 + 2 * KTILE_B)     // 15360, 2 buffers
#define SMEM_TOTAL (OFF_V + 2 * VTILE_B)  // 82944

__device__ __forceinline__ void flash_load_chunk(char* smem_raw, int buf, int b, int j0, int tid) {
    __half* k_s = (__half*)(smem_raw + OFF_K + buf * KTILE_B);
    __half* v_s = (__half*)(smem_raw + OFF_V + buf * VTILE_B);
    {   // K chunk 64x32
        int e = tid * 8;
        int r = e >> 5, c = e & 31;
        cp_async16(smem_u32(&k_s[r * 40 + c]),
                   &g_kT[((size_t)b * NPIX + j0 + r) * 32 + c]);
    }
#pragma unroll
    for (int p = 0; p < 8; p++) {  // V chunk 64x256
        int e = (tid + p * 256) * 8;
        int r = e >> 8, c = e & 255;
        cp_async16(smem_u32(&v_s[r * VSTR + c]),
                   &g_vT[((size_t)b * NPIX + j0 + r) * NC + c]);
    }
}

__global__ __launch_bounds__(256) void flash_kernel(float* __restrict__ out) {
    extern __shared__ char smem_raw[];
    __half* q_s = (__half*)(smem_raw + OFF_Q);

    int nq0 = blockIdx.x * 64;
    int b   = blockIdx.y;
    int tid = threadIdx.x;
    int w = tid >> 5, lane = tid & 31, g = lane >> 2, t4 = lane & 3;
    int mw = w & 3;       // query row group: rows [16*mw, 16*mw+16)
    int nh = w >> 2;      // channel half for PV: chans [128*nh, +128)

    {   // load Q tile (64x32)
        int e = tid * 8;
        int r = e >> 5, c = e & 31;
        *(uint4*)&q_s[r * 40 + c] = *(const uint4*)&g_qT[((size_t)b * NPIX + nq0 + r) * 32 + c];
    }

    // prefetch chunk 0
    flash_load_chunk(smem_raw, 0, b, 0, tid);
    cp_commit();

    float acc[16][4];
#pragma unroll
    for (int i = 0; i < 16; i++)
#pragma unroll
        for (int j = 0; j < 4; j++) acc[i][j] = 0.f;
    float m0 = -1e30f, m1 = -1e30f, l0 = 0.f, l1 = 0.f;

    __syncthreads();  // Q visible
    // Q fragments (constant across key chunks)
    uint32_t qa[2][4];
#pragma unroll
    for (int ks = 0; ks < 2; ks++) {
        int row = 16 * mw + (lane & 15);
        int col = 16 * ks + ((lane >= 16) ? 8 : 0);
        ldm_x4(qa[ks], smem_u32(&q_s[row * 40 + col]));
    }

    const int NCHUNK = NPIX / 64;
    for (int kc = 0; kc < NCHUNK; kc++) {
        int buf = kc & 1;
        if (kc + 1 < NCHUNK) {
            flash_load_chunk(smem_raw, buf ^ 1, b, (kc + 1) * 64, tid);
            cp_commit();
            cp_wait<1>();
        } else {
            cp_wait<0>();
        }
        __syncthreads();  // chunk kc visible to all

        __half* k_s = (__half*)(smem_raw + OFF_K + buf * KTILE_B);
        __half* v_s = (__half*)(smem_raw + OFF_V + buf * VTILE_B);

        // ---- S = Q K^T : 16 rows x 64 keys, all in registers ----
        float sacc[8][4];
#pragma unroll
        for (int i = 0; i < 8; i++)
#pragma unroll
            for (int j = 0; j < 4; j++) sacc[i][j] = 0.f;
#pragma unroll
        for (int ks = 0; ks < 2; ks++) {
#pragma unroll
            for (int nbp = 0; nbp < 4; nbp++) {
                uint32_t bf[4];
                int key = nbp * 16 + (lane & 7) + ((lane >= 16) ? 8 : 0);
                int col = 16 * ks + ((lane & 8) ? 8 : 0);
                ldm_x4(bf, smem_u32(&k_s[key * 40 + col]));
                mma_16816(sacc[2 * nbp],     qa[ks], bf[0], bf[1]);
                mma_16816(sacc[2 * nbp + 1], qa[ks], bf[2], bf[3]);
            }
        }

        // ---- online softmax in registers ----
        // row r0 = 16*mw + g (vals [0],[1]); row r1 = r0+8 (vals [2],[3])
        float mx0 = sacc[0][0], mx1 = sacc[0][2];
#pragma unroll
        for (int j = 0; j < 8; j++) {
            mx0 = fmaxf(mx0, fmaxf(sacc[j][0], sacc[j][1]));
            mx1 = fmaxf(mx1, fmaxf(sacc[j][2], sacc[j][3]));
        }
#pragma unroll
        for (int off = 1; off < 4; off <<= 1) {
            mx0 = fmaxf(mx0, __shfl_xor_sync(0xffffffffu, mx0, off));
            mx1 = fmaxf(mx1, __shfl_xor_sync(0xffffffffu, mx1, off));
        }
        float mn0 = fmaxf(m0, mx0), mn1 = fmaxf(m1, mx1);
        float al0 = __expf(m0 - mn0), al1 = __expf(m1 - mn1);
        m0 = mn0; m1 = mn1;
        float sum0 = 0.f, sum1 = 0.f;
#pragma unroll
        for (int j = 0; j < 8; j++) {
            sacc[j][0] = __expf(sacc[j][0] - mn0);
            sacc[j][1] = __expf(sacc[j][1] - mn0);
            sacc[j][2] = __expf(sacc[j][2] - mn1);
            sacc[j][3] = __expf(sacc[j][3] - mn1);
            sum0 += sacc[j][0] + sacc[j][1];
            sum1 += sacc[j][2] + sacc[j][3];
        }
#pragma unroll
        for (int off = 1; off < 4; off <<= 1) {
            sum0 += __shfl_xor_sync(0xffffffffu, sum0, off);
            sum1 += __shfl_xor_sync(0xffffffffu, sum1, off);
        }
        l0 = l0 * al0 + sum0;
        l1 = l1 * al1 + sum1;

        // rescale O accumulators
#pragma unroll
        for (int nt = 0; nt < 16; nt++) {
            acc[nt][0] *= al0; acc[nt][1] *= al0;
            acc[nt][2] *= al1; acc[nt][3] *= al1;
        }

        // pack P fragments (C-layout == A-layout)
        uint32_t pa[4][4];
#pragma unroll
        for (int ks = 0; ks < 4; ks++) {
            pa[ks][0] = h2_as_u32(__floats2half2_rn(sacc[2 * ks][0],     sacc[2 * ks][1]));
            pa[ks][1] = h2_as_u32(__floats2half2_rn(sacc[2 * ks][2],     sacc[2 * ks][3]));
            pa[ks][2] = h2_as_u32(__floats2half2_rn(sacc[2 * ks + 1][0], sacc[2 * ks + 1][1]));
            pa[ks][3] = h2_as_u32(__floats2half2_rn(sacc[2 * ks + 1][2], sacc[2 * ks + 1][3]));
        }

        // ---- O += P V : 16 rows x 128 channels ----
#pragma unroll
        for (int ks = 0; ks < 4; ks++) {
#pragma unroll
            for (int nbp = 0; nbp < 8; nbp++) {
                uint32_t bf[4];
                int key  = 16 * ks + (lane & 15);
                int chan = nh * 128 + 16 * nbp + ((lane >= 16) ? 8 : 0);
                ldm_x4_t(bf, smem_u32(&v_s[key * VSTR + chan]));
                mma_16816(acc[2 * nbp],     pa[ks], bf[0], bf[1]);
                mma_16816(acc[2 * nbp + 1], pa[ks], bf[2], bf[3]);
            }
        }
        __syncthreads();  // all reads of buf done before next prefetch overwrites it
    }

    // ---- finalize: divide by l, stage transposed, coalesced write ----
    float* o_s = (float*)smem_raw;  // [64][260] = 66560B, reuses all buffers
    {
        int ra = 16 * mw + g;
        float inv0 = 1.f / l0;
        float inv1 = 1.f / l1;
#pragma unroll
        for (int nt = 0; nt < 16; nt++) {
            int col = nh * 128 + 8 * nt + 2 * t4;
            o_s[ra * 260 + col]           = acc[nt][0] * inv0;
            o_s[ra * 260 + col + 1]       = acc[nt][1] * inv0;
            o_s[(ra + 8) * 260 + col]     = acc[nt][2] * inv1;
            o_s[(ra + 8) * 260 + col + 1] = acc[nt][3] * inv1;
        }
    }
    __syncthreads();
    int nl = tid & 63;
    int cb = tid >> 6;  // 0..3
#pragma unroll
    for (int it = 0; it < 64; it++) {
        int c = it * 4 + cb;
        out[((size_t)b * NC + c) * NPIX + nq0 + nl] = o_s[nl * 260 + c];
    }
}

// ---------------- launcher ----------------
extern "C" void kernel_launch(void* const* d_in, const int* in_sizes, int n_in,
                              void* d_out, int out_size) {
    (void)in_sizes; (void)n_in; (void)out_size;
    const float* x  = (const float*)d_in[0];
    const float* wq = (const float*)d_in[1];
    const float* bq = (const float*)d_in[2];
    const float* wk = (const float*)d_in[3];
    const float* bk = (const float*)d_in[4];
    const float* wv = (const float*)d_in[5];
    const float* bv = (const float*)d_in[6];
    float* out = (float*)d_out;

    pack_w_kernel<<<(MR * NC + 255) / 256, 256>>>(wq, wk, wv);
    pack_x_kernel<<<(NB * NC * NPIX / 4 + 255) / 256, 256>>>(x);

    dim3 pg(NPIX / 64, MR / 64, NB);
    proj_kernel<<<pg, 128>>>(bq, bk, bv);

    cudaFuncSetAttribute(flash_kernel, cudaFuncAttributeMaxDynamicSharedMemorySize, SMEM_TOTAL);
    dim3 fg(NPIX / 64, NB);
    flash_kernel<<<fg, 256, SMEM_TOTAL>>>(out);
}

// round 4
// speedup vs baseline: 2.3385x; 1.0961x over previous
#include <cuda_runtime.h>
#include <cuda_fp16.h>
#include <stdint.h>

#define NB   8
#define NC   256
#define NPIX 4096
#define KST  768      // stacked K: [x_h; x_l; x_h(reused)]
#define KSL  512      // stored slabs (hi, lo)
#define MR   320      // 32 q + 32 k + 256 v output channels
#define LOG2E 1.4426950408889634f

// ---------------- scratch (device globals; no allocation) ----------------
__device__ __half g_xs[(size_t)NB * KSL * NPIX];   // 33.5 MB stacked x (fp16 hi/lo)
__device__ __half g_ws[MR * KST];                  // stacked weights
__device__ __half g_qT[(size_t)NB * NPIX * 32];    // [b][n][d]  (q pre-scaled by log2e)
__device__ __half g_kT[(size_t)NB * NPIX * 32];    // [b][n][d]
__device__ __half g_vT[(size_t)NB * NPIX * NC];    // [b][n][c]

// ---------------- mma / ldmatrix / cp.async helpers ----------------
__device__ __forceinline__ unsigned smem_u32(const void* p) {
    return (unsigned)__cvta_generic_to_shared(p);
}
__device__ __forceinline__ uint32_t h2_as_u32(__half2 h) {
    return *reinterpret_cast<uint32_t*>(&h);
}
__device__ __forceinline__ uint32_t h2exp2(uint32_t x) {
    uint32_t r;
    asm("ex2.approx.f16x2 %0, %1;" : "=r"(r) : "r"(x));
    return r;
}
__device__ __forceinline__ float ex2f(float x) {
    float r;
    asm("ex2.approx.f32 %0, %1;" : "=f"(r) : "f"(x));
    return r;
}
__device__ __forceinline__ void ldm_x4(uint32_t* r, unsigned addr) {
    asm volatile("ldmatrix.sync.aligned.m8n8.x4.shared.b16 {%0,%1,%2,%3}, [%4];\n"
                 : "=r"(r[0]), "=r"(r[1]), "=r"(r[2]), "=r"(r[3]) : "r"(addr));
}
__device__ __forceinline__ void ldm_x4_t(uint32_t* r, unsigned addr) {
    asm volatile("ldmatrix.sync.aligned.m8n8.x4.trans.shared.b16 {%0,%1,%2,%3}, [%4];\n"
                 : "=r"(r[0]), "=r"(r[1]), "=r"(r[2]), "=r"(r[3]) : "r"(addr));
}
__device__ __forceinline__ void mma_16816(float* d, const uint32_t* a, uint32_t b0, uint32_t b1) {
    asm volatile(
        "mma.sync.aligned.m16n8k16.row.col.f32.f16.f16.f32 "
        "{%0,%1,%2,%3},{%4,%5,%6,%7},{%8,%9},{%0,%1,%2,%3};\n"
        : "+f"(d[0]), "+f"(d[1]), "+f"(d[2]), "+f"(d[3])
        : "r"(a[0]), "r"(a[1]), "r"(a[2]), "r"(a[3]), "r"(b0), "r"(b1));
}
__device__ __forceinline__ void cp_async16(unsigned dst, const void* src) {
    asm volatile("cp.async.cg.shared.global [%0], [%1], 16;\n" :: "r"(dst), "l"(src));
}
__device__ __forceinline__ void cp_commit() {
    asm volatile("cp.async.commit_group;\n");
}
template <int N>
__device__ __forceinline__ void cp_wait() {
    asm volatile("cp.async.wait_group %0;\n" :: "n"(N));
}

// ---------------- pack kernels ----------------
__global__ void pack_w_kernel(const float* __restrict__ wq, const float* __restrict__ wk,
                              const float* __restrict__ wv) {
    int idx = blockIdx.x * blockDim.x + threadIdx.x;
    if (idx >= MR * NC) return;
    int k = idx & 255;
    int m = idx >> 8;
    float w = (m < 32) ? wq[m * NC + k] * LOG2E
            : (m < 64) ? wk[(m - 32) * NC + k]
                       : wv[(m - 64) * NC + k];
    __half hi = __float2half_rn(w);
    __half lo = __float2half_rn(w - __half2float(hi));
    g_ws[m * KST + k]       = hi;   // pairs with x_h
    g_ws[m * KST + 256 + k] = hi;   // pairs with x_l
    g_ws[m * KST + 512 + k] = lo;   // pairs with x_h (re-read slab 0)
}

__global__ void pack_x_kernel(const float* __restrict__ x) {
    int idx = blockIdx.x * blockDim.x + threadIdx.x;  // one float4 each
    const int total = NB * NC * NPIX / 4;
    if (idx >= total) return;
    float4 v = ((const float4*)x)[idx];
    int n4 = idx % (NPIX / 4);
    int t  = idx / (NPIX / 4);
    int c  = t % NC;
    int b  = t / NC;
    float f[4] = {v.x, v.y, v.z, v.w};
    __align__(8) __half hi[4], lo[4];
#pragma unroll
    for (int i = 0; i < 4; i++) {
        hi[i] = __float2half_rn(f[i]);
        lo[i] = __float2half_rn(f[i] - __half2float(hi[i]));
    }
    size_t base = ((size_t)b * KSL) * NPIX + (size_t)n4 * 4;
    *(uint2*)&g_xs[base + (size_t)c * NPIX]         = *(uint2*)&hi[0];
    *(uint2*)&g_xs[base + (size_t)(c + 256) * NPIX] = *(uint2*)&lo[0];
}

// ---------------- projection GEMM: C[320,4096] = Ws[320,768] * Xs[768,4096] ----------------
#define PA_STR 40
#define PB_STR 72

__global__ __launch_bounds__(128) void proj_kernel(const float* __restrict__ bq,
                                                   const float* __restrict__ bk,
                                                   const float* __restrict__ bv) {
    __shared__ __half a_s[64 * PA_STR];
    __shared__ __half b_s[32 * PB_STR];
    __shared__ __half c_s[64 * PB_STR];

    int n0 = blockIdx.x * 64;
    int m0 = blockIdx.y * 64;
    int b  = blockIdx.z;
    int tid = threadIdx.x;
    int w = tid >> 5, lane = tid & 31;
    int g = lane >> 2, t4 = lane & 3;

    float acc[8][4];
#pragma unroll
    for (int i = 0; i < 8; i++)
#pragma unroll
        for (int j = 0; j < 4; j++) acc[i][j] = 0.f;

    const __half* gA = &g_ws[m0 * KST];
    const __half* gB = &g_xs[(size_t)b * KSL * NPIX + n0];

    for (int kt = 0; kt < KST / 32; kt++) {
        int k0 = kt * 32;
        int kk = (k0 < KSL) ? k0 : (k0 - KSL);  // hi slab re-read for lo-weight rows
        __syncthreads();
#pragma unroll
        for (int p = 0; p < 2; p++) {  // A: 64x32
            int e = (tid + p * 128) * 8;
            int r = e >> 5, c = e & 31;
            *(uint4*)&a_s[r * PA_STR + c] = *(const uint4*)&gA[r * KST + k0 + c];
        }
#pragma unroll
        for (int p = 0; p < 2; p++) {  // B: 32x64
            int e = (tid + p * 128) * 8;
            int r = e >> 6, c = e & 63;
            *(uint4*)&b_s[r * PB_STR + c] = *(const uint4*)&gB[(size_t)(kk + r) * NPIX + c];
        }
        __syncthreads();
#pragma unroll
        for (int ks = 0; ks < 2; ks++) {
            uint32_t af[4];
            {
                int row = 16 * w + (lane & 15);
                int col = 16 * ks + ((lane >= 16) ? 8 : 0);
                ldm_x4(af, smem_u32(&a_s[row * PA_STR + col]));
            }
#pragma unroll
            for (int nbp = 0; nbp < 4; nbp++) {
                uint32_t bf[4];
                int row = 16 * ks + (lane & 15);
                int col = 16 * nbp + ((lane >= 16) ? 8 : 0);
                ldm_x4_t(bf, smem_u32(&b_s[row * PB_STR + col]));
                mma_16816(acc[2 * nbp],     af, bf[0], bf[1]);
                mma_16816(acc[2 * nbp + 1], af, bf[2], bf[3]);
            }
        }
    }
    __syncthreads();
    // bias + fp16 stage
    int row_a = 16 * w + g;
    int row_b = row_a + 8;
    int ma = m0 + row_a, mb = m0 + row_b;
    float bias_a = (ma < 32) ? bq[ma] * LOG2E : (ma < 64) ? bk[ma - 32] : bv[ma - 64];
    float bias_b = (mb < 32) ? bq[mb] * LOG2E : (mb < 64) ? bk[mb - 32] : bv[mb - 64];
#pragma unroll
    for (int nt = 0; nt < 8; nt++) {
        int col = 8 * nt + 2 * t4;
        c_s[row_a * PB_STR + col]     = __float2half_rn(acc[nt][0] + bias_a);
        c_s[row_a * PB_STR + col + 1] = __float2half_rn(acc[nt][1] + bias_a);
        c_s[row_b * PB_STR + col]     = __float2half_rn(acc[nt][2] + bias_b);
        c_s[row_b * PB_STR + col + 1] = __float2half_rn(acc[nt][3] + bias_b);
    }
    __syncthreads();
    // transposed coalesced writeback
    int n = tid & 63, part = tid >> 6;
    __align__(16) __half tmp[32];
#pragma unroll
    for (int j = 0; j < 32; j++) tmp[j] = c_s[(part * 32 + j) * PB_STR + n];
    int ng = n0 + n;
    __half* dst;
    if (m0 == 0) {
        dst = (part == 0) ? &g_qT[((size_t)b * NPIX + ng) * 32]
                          : &g_kT[((size_t)b * NPIX + ng) * 32];
    } else {
        int cb = (m0 - 64) + part * 32;
        dst = &g_vT[((size_t)b * NPIX + ng) * NC + cb];
    }
#pragma unroll
    for (int q = 0; q < 4; q++) ((uint4*)dst)[q] = ((uint4*)tmp)[q];
}

// ---------------- flash attention: 64 queries x 128-key chunks ----------------
#define CK   128                       // keys per chunk
#define VSTR 264
#define KTILE_B (CK * 40 * 2)          // 10240
#define VTILE_B (CK * VSTR * 2)        // 67584
#define OFF_Q 0
#define OFF_K 5120                     // 2 buffers
#define OFF_V (OFF_K + 2 * KTILE_B)    // 25600, 2 buffers
#define SMEM_TOTAL (OFF_V + 2 * VTILE_B)  // 160768
#define ONES_H2 0x3C003C00u

__device__ __forceinline__ void flash_load_chunk(char* smem_raw, int buf, int b, int j0, int tid) {
    __half* k_s = (__half*)(smem_raw + OFF_K + buf * KTILE_B);
    __half* v_s = (__half*)(smem_raw + OFF_V + buf * VTILE_B);
#pragma unroll
    for (int p = 0; p < 2; p++) {  // K chunk 128x32
        int e = (tid + p * 256) * 8;
        int r = e >> 5, c = e & 31;
        cp_async16(smem_u32(&k_s[r * 40 + c]),
                   &g_kT[((size_t)b * NPIX + j0 + r) * 32 + c]);
    }
#pragma unroll
    for (int p = 0; p < 16; p++) {  // V chunk 128x256
        int e = (tid + p * 256) * 8;
        int r = e >> 8, c = e & 255;
        cp_async16(smem_u32(&v_s[r * VSTR + c]),
                   &g_vT[((size_t)b * NPIX + j0 + r) * NC + c]);
    }
}

__global__ __launch_bounds__(256) void flash_kernel(float* __restrict__ out) {
    extern __shared__ char smem_raw[];
    __half* q_s = (__half*)(smem_raw + OFF_Q);

    int nq0 = blockIdx.x * 64;
    int b   = blockIdx.y;
    int tid = threadIdx.x;
    int w = tid >> 5, lane = tid & 31, g = lane >> 2, t4 = lane & 3;
    int mw = w & 3;       // query row group: rows [16*mw, 16*mw+16)
    int nh = w >> 2;      // channel half for PV: chans [128*nh, +128)

    {   // load Q tile (64x32)
        int e = tid * 8;
        int r = e >> 5, c = e & 31;
        *(uint4*)&q_s[r * 40 + c] = *(const uint4*)&g_qT[((size_t)b * NPIX + nq0 + r) * 32 + c];
    }

    // prefetch chunk 0
    flash_load_chunk(smem_raw, 0, b, 0, tid);
    cp_commit();

    float acc[16][4];
#pragma unroll
    for (int i = 0; i < 16; i++)
#pragma unroll
        for (int j = 0; j < 4; j++) acc[i][j] = 0.f;
    float lacc[4] = {0.f, 0.f, 0.f, 0.f};
    float m0 = -1e30f, m1 = -1e30f;

    __syncthreads();  // Q visible
    // Q fragments (constant across key chunks)
    uint32_t qa[2][4];
#pragma unroll
    for (int ks = 0; ks < 2; ks++) {
        int row = 16 * mw + (lane & 15);
        int col = 16 * ks + ((lane >= 16) ? 8 : 0);
        ldm_x4(qa[ks], smem_u32(&q_s[row * 40 + col]));
    }

    const int NCHUNK = NPIX / CK;  // 32
#pragma unroll 1
    for (int kc = 0; kc < NCHUNK; kc++) {
        int buf = kc & 1;
        cp_wait<0>();
        __syncthreads();  // chunk kc visible; all warps done reading buf^1
        if (kc + 1 < NCHUNK) {
            flash_load_chunk(smem_raw, buf ^ 1, b, (kc + 1) * CK, tid);
            cp_commit();
        }

        __half* k_s = (__half*)(smem_raw + OFF_K + buf * KTILE_B);
        __half* v_s = (__half*)(smem_raw + OFF_V + buf * VTILE_B);

        // ---- S' = Q' K^T (log2 domain): 16 rows x 128 keys, in registers ----
        float sacc[16][4];
#pragma unroll
        for (int i = 0; i < 16; i++)
#pragma unroll
            for (int j = 0; j < 4; j++) sacc[i][j] = 0.f;
#pragma unroll
        for (int ks = 0; ks < 2; ks++) {
#pragma unroll
            for (int nbp = 0; nbp < 8; nbp++) {
                uint32_t bf[4];
                int key = nbp * 16 + (lane & 7) + ((lane >= 16) ? 8 : 0);
                int col = 16 * ks + ((lane & 8) ? 8 : 0);
                ldm_x4(bf, smem_u32(&k_s[key * 40 + col]));
                mma_16816(sacc[2 * nbp],     qa[ks], bf[0], bf[1]);
                mma_16816(sacc[2 * nbp + 1], qa[ks], bf[2], bf[3]);
            }
        }

        // ---- online softmax (base-2, fp16 exp) ----
        float mx0 = sacc[0][0], mx1 = sacc[0][2];
#pragma unroll
        for (int j = 0; j < 16; j++) {
            mx0 = fmaxf(mx0, fmaxf(sacc[j][0], sacc[j][1]));
            mx1 = fmaxf(mx1, fmaxf(sacc[j][2], sacc[j][3]));
        }
#pragma unroll
        for (int off = 1; off < 4; off <<= 1) {
            mx0 = fmaxf(mx0, __shfl_xor_sync(0xffffffffu, mx0, off));
            mx1 = fmaxf(mx1, __shfl_xor_sync(0xffffffffu, mx1, off));
        }
        float mn0 = fmaxf(m0, mx0), mn1 = fmaxf(m1, mx1);
        float al0 = ex2f(m0 - mn0), al1 = ex2f(m1 - mn1);
        m0 = mn0; m1 = mn1;

        // exp via f16x2 ex2 — output IS the packed P fragment
        uint32_t pa[8][4];
#pragma unroll
        for (int ks = 0; ks < 8; ks++) {
            pa[ks][0] = h2exp2(h2_as_u32(__floats2half2_rn(sacc[2 * ks][0] - mn0,     sacc[2 * ks][1] - mn0)));
            pa[ks][1] = h2exp2(h2_as_u32(__floats2half2_rn(sacc[2 * ks][2] - mn1,     sacc[2 * ks][3] - mn1)));
            pa[ks][2] = h2exp2(h2_as_u32(__floats2half2_rn(sacc[2 * ks + 1][0] - mn0, sacc[2 * ks + 1][1] - mn0)));
            pa[ks][3] = h2exp2(h2_as_u32(__floats2half2_rn(sacc[2 * ks + 1][2] - mn1, sacc[2 * ks + 1][3] - mn1)));
        }

        // rescale O accumulators and l accumulators
#pragma unroll
        for (int nt = 0; nt < 16; nt++) {
            acc[nt][0] *= al0; acc[nt][1] *= al0;
            acc[nt][2] *= al1; acc[nt][3] *= al1;
        }
        lacc[0] *= al0; lacc[1] *= al0; lacc[2] *= al1; lacc[3] *= al1;

        // ---- O += P V : 16 rows x 128 channels ----
#pragma unroll
        for (int ks = 0; ks < 8; ks++) {
#pragma unroll
            for (int nbp = 0; nbp < 8; nbp++) {
                uint32_t bf[4];
                int key  = 16 * ks + (lane & 15);
                int chan = nh * 128 + 16 * nbp + ((lane >= 16) ? 8 : 0);
                ldm_x4_t(bf, smem_u32(&v_s[key * VSTR + chan]));
                mma_16816(acc[2 * nbp],     pa[ks], bf[0], bf[1]);
                mma_16816(acc[2 * nbp + 1], pa[ks], bf[2], bf[3]);
            }
        }
        // ---- l += P . 1 (row sums via tensor core) ----
#pragma unroll
        for (int ks = 0; ks < 8; ks++)
            mma_16816(lacc, pa[ks], ONES_H2, ONES_H2);
    }

    float l0 = lacc[0], l1 = lacc[2];

    // ---- finalize: divide by l, stage transposed, coalesced write ----
    __syncthreads();
    float* o_s = (float*)smem_raw;  // [64][260] = 66560B, reuses all buffers
    {
        int ra = 16 * mw + g;
        float inv0 = 1.f / l0;
        float inv1 = 1.f / l1;
#pragma unroll
        for (int nt = 0; nt < 16; nt++) {
            int col = nh * 128 + 8 * nt + 2 * t4;
            o_s[ra * 260 + col]           = acc[nt][0] * inv0;
            o_s[ra * 260 + col + 1]       = acc[nt][1] * inv0;
            o_s[(ra + 8) * 260 + col]     = acc[nt][2] * inv1;
            o_s[(ra + 8) * 260 + col + 1] = acc[nt][3] * inv1;
        }
    }
    __syncthreads();
    int nl = tid & 63;
    int cb = tid >> 6;  // 0..3
#pragma unroll
    for (int it = 0; it < 64; it++) {
        int c = it * 4 + cb;
        out[((size_t)b * NC + c) * NPIX + nq0 + nl] = o_s[nl * 260 + c];
    }
}

// ---------------- launcher ----------------
extern "C" void kernel_launch(void* const* d_in, const int* in_sizes, int n_in,
                              void* d_out, int out_size) {
    (void)in_sizes; (void)n_in; (void)out_size;
    const float* x  = (const float*)d_in[0];
    const float* wq = (const float*)d_in[1];
    const float* bq = (const float*)d_in[2];
    const float* wk = (const float*)d_in[3];
    const float* bk = (const float*)d_in[4];
    const float* wv = (const float*)d_in[5];
    const float* bv = (const float*)d_in[6];
    float* out = (float*)d_out;

    pack_w_kernel<<<(MR * NC + 255) / 256, 256>>>(wq, wk, wv);
    pack_x_kernel<<<(NB * NC * NPIX / 4 + 255) / 256, 256>>>(x);

    dim3 pg(NPIX / 64, MR / 64, NB);
    proj_kernel<<<pg, 128>>>(bq, bk, bv);

    cudaFuncSetAttribute(flash_kernel, cudaFuncAttributeMaxDynamicSharedMemorySize, SMEM_TOTAL);
    dim3 fg(NPIX / 64, NB);
    flash_kernel<<<fg, 256, SMEM_TOTAL>>>(out);
}

// round 5
// speedup vs baseline: 2.3678x; 1.0125x over previous
#include <cuda_runtime.h>
#include <cuda_fp16.h>
#include <stdint.h>

#define NB   8
#define NC   256
#define NPIX 4096
#define KST  768      // stacked K: [x_h; x_l; x_h(reused)]
#define KSL  512      // stored slabs (hi, lo)
#define MR   320      // 32 q + 32 k + 256 v output channels
#define LOG2E 1.4426950408889634f

// ---------------- scratch (device globals; no allocation) ----------------
__device__ __half g_xs[(size_t)NB * KSL * NPIX];   // 33.5 MB stacked x (fp16 hi/lo)
__device__ __half g_ws[MR * KST];                  // stacked weights
__device__ __half g_qT[(size_t)NB * NPIX * 32];    // [b][n][d]  (q pre-scaled by log2e)
__device__ __half g_kT[(size_t)NB * NPIX * 32];    // [b][n][d]
__device__ __half g_vT[(size_t)NB * NPIX * NC];    // [b][n][c]

// ---------------- mma / ldmatrix / cp.async helpers ----------------
__device__ __forceinline__ unsigned smem_u32(const void* p) {
    return (unsigned)__cvta_generic_to_shared(p);
}
__device__ __forceinline__ uint32_t h2_as_u32(__half2 h) {
    return *reinterpret_cast<uint32_t*>(&h);
}
__device__ __forceinline__ uint32_t h2exp2(uint32_t x) {
    uint32_t r;
    asm("ex2.approx.f16x2 %0, %1;" : "=r"(r) : "r"(x));
    return r;
}
__device__ __forceinline__ float ex2f(float x) {
    float r;
    asm("ex2.approx.f32 %0, %1;" : "=f"(r) : "f"(x));
    return r;
}
__device__ __forceinline__ void ldm_x4(uint32_t* r, unsigned addr) {
    asm volatile("ldmatrix.sync.aligned.m8n8.x4.shared.b16 {%0,%1,%2,%3}, [%4];\n"
                 : "=r"(r[0]), "=r"(r[1]), "=r"(r[2]), "=r"(r[3]) : "r"(addr));
}
__device__ __forceinline__ void ldm_x4_t(uint32_t* r, unsigned addr) {
    asm volatile("ldmatrix.sync.aligned.m8n8.x4.trans.shared.b16 {%0,%1,%2,%3}, [%4];\n"
                 : "=r"(r[0]), "=r"(r[1]), "=r"(r[2]), "=r"(r[3]) : "r"(addr));
}
__device__ __forceinline__ void mma_16816(float* d, const uint32_t* a, uint32_t b0, uint32_t b1) {
    asm volatile(
        "mma.sync.aligned.m16n8k16.row.col.f32.f16.f16.f32 "
        "{%0,%1,%2,%3},{%4,%5,%6,%7},{%8,%9},{%0,%1,%2,%3};\n"
        : "+f"(d[0]), "+f"(d[1]), "+f"(d[2]), "+f"(d[3])
        : "r"(a[0]), "r"(a[1]), "r"(a[2]), "r"(a[3]), "r"(b0), "r"(b1));
}
__device__ __forceinline__ void cp_async16(unsigned dst, const void* src) {
    asm volatile("cp.async.cg.shared.global [%0], [%1], 16;\n" :: "r"(dst), "l"(src));
}
__device__ __forceinline__ void cp_commit() {
    asm volatile("cp.async.commit_group;\n");
}
template <int N>
__device__ __forceinline__ void cp_wait() {
    asm volatile("cp.async.wait_group %0;\n" :: "n"(N));
}

// ---------------- pack kernels ----------------
__global__ void pack_w_kernel(const float* __restrict__ wq, const float* __restrict__ wk,
                              const float* __restrict__ wv) {
    int idx = blockIdx.x * blockDim.x + threadIdx.x;
    if (idx >= MR * NC) return;
    int k = idx & 255;
    int m = idx >> 8;
    float w = (m < 32) ? wq[m * NC + k] * LOG2E
            : (m < 64) ? wk[(m - 32) * NC + k]
                       : wv[(m - 64) * NC + k];
    __half hi = __float2half_rn(w);
    __half lo = __float2half_rn(w - __half2float(hi));
    g_ws[m * KST + k]       = hi;   // pairs with x_h
    g_ws[m * KST + 256 + k] = hi;   // pairs with x_l
    g_ws[m * KST + 512 + k] = lo;   // pairs with x_h (re-read slab 0)
}

__global__ void pack_x_kernel(const float* __restrict__ x) {
    int idx = blockIdx.x * blockDim.x + threadIdx.x;  // one float4 each
    const int total = NB * NC * NPIX / 4;
    if (idx >= total) return;
    float4 v = ((const float4*)x)[idx];
    int n4 = idx % (NPIX / 4);
    int t  = idx / (NPIX / 4);
    int c  = t % NC;
    int b  = t / NC;
    float f[4] = {v.x, v.y, v.z, v.w};
    __align__(8) __half hi[4], lo[4];
#pragma unroll
    for (int i = 0; i < 4; i++) {
        hi[i] = __float2half_rn(f[i]);
        lo[i] = __float2half_rn(f[i] - __half2float(hi[i]));
    }
    size_t base = ((size_t)b * KSL) * NPIX + (size_t)n4 * 4;
    *(uint2*)&g_xs[base + (size_t)c * NPIX]         = *(uint2*)&hi[0];
    *(uint2*)&g_xs[base + (size_t)(c + 256) * NPIX] = *(uint2*)&lo[0];
}

// ---------------- projection GEMM: C[320,4096] = Ws[320,768] * Xs[768,4096] ----------------
#define PA_STR 40
#define PB_STR 72

__global__ __launch_bounds__(128) void proj_kernel(const float* __restrict__ bq,
                                                   const float* __restrict__ bk,
                                                   const float* __restrict__ bv) {
    __shared__ __half a_s[64 * PA_STR];
    __shared__ __half b_s[32 * PB_STR];
    __shared__ __half c_s[64 * PB_STR];

    int n0 = blockIdx.x * 64;
    int m0 = blockIdx.y * 64;
    int b  = blockIdx.z;
    int tid = threadIdx.x;
    int w = tid >> 5, lane = tid & 31;
    int g = lane >> 2, t4 = lane & 3;

    float acc[8][4];
#pragma unroll
    for (int i = 0; i < 8; i++)
#pragma unroll
        for (int j = 0; j < 4; j++) acc[i][j] = 0.f;

    const __half* gA = &g_ws[m0 * KST];
    const __half* gB = &g_xs[(size_t)b * KSL * NPIX + n0];

    for (int kt = 0; kt < KST / 32; kt++) {
        int k0 = kt * 32;
        int kk = (k0 < KSL) ? k0 : (k0 - KSL);  // hi slab re-read for lo-weight rows
        __syncthreads();
#pragma unroll
        for (int p = 0; p < 2; p++) {  // A: 64x32
            int e = (tid + p * 128) * 8;
            int r = e >> 5, c = e & 31;
            *(uint4*)&a_s[r * PA_STR + c] = *(const uint4*)&gA[r * KST + k0 + c];
        }
#pragma unroll
        for (int p = 0; p < 2; p++) {  // B: 32x64
            int e = (tid + p * 128) * 8;
            int r = e >> 6, c = e & 63;
            *(uint4*)&b_s[r * PB_STR + c] = *(const uint4*)&gB[(size_t)(kk + r) * NPIX + c];
        }
        __syncthreads();
#pragma unroll
        for (int ks = 0; ks < 2; ks++) {
            uint32_t af[4];
            {
                int row = 16 * w + (lane & 15);
                int col = 16 * ks + ((lane >= 16) ? 8 : 0);
                ldm_x4(af, smem_u32(&a_s[row * PA_STR + col]));
            }
#pragma unroll
            for (int nbp = 0; nbp < 4; nbp++) {
                uint32_t bf[4];
                int row = 16 * ks + (lane & 15);
                int col = 16 * nbp + ((lane >= 16) ? 8 : 0);
                ldm_x4_t(bf, smem_u32(&b_s[row * PB_STR + col]));
                mma_16816(acc[2 * nbp],     af, bf[0], bf[1]);
                mma_16816(acc[2 * nbp + 1], af, bf[2], bf[3]);
            }
        }
    }
    __syncthreads();
    // bias + fp16 stage
    int row_a = 16 * w + g;
    int row_b = row_a + 8;
    int ma = m0 + row_a, mb = m0 + row_b;
    float bias_a = (ma < 32) ? bq[ma] * LOG2E : (ma < 64) ? bk[ma - 32] : bv[ma - 64];
    float bias_b = (mb < 32) ? bq[mb] * LOG2E : (mb < 64) ? bk[mb - 32] : bv[mb - 64];
#pragma unroll
    for (int nt = 0; nt < 8; nt++) {
        int col = 8 * nt + 2 * t4;
        c_s[row_a * PB_STR + col]     = __float2half_rn(acc[nt][0] + bias_a);
        c_s[row_a * PB_STR + col + 1] = __float2half_rn(acc[nt][1] + bias_a);
        c_s[row_b * PB_STR + col]     = __float2half_rn(acc[nt][2] + bias_b);
        c_s[row_b * PB_STR + col + 1] = __float2half_rn(acc[nt][3] + bias_b);
    }
    __syncthreads();
    // transposed coalesced writeback
    int n = tid & 63, part = tid >> 6;
    __align__(16) __half tmp[32];
#pragma unroll
    for (int j = 0; j < 32; j++) tmp[j] = c_s[(part * 32 + j) * PB_STR + n];
    int ng = n0 + n;
    __half* dst;
    if (m0 == 0) {
        dst = (part == 0) ? &g_qT[((size_t)b * NPIX + ng) * 32]
                          : &g_kT[((size_t)b * NPIX + ng) * 32];
    } else {
        int cb = (m0 - 64) + part * 32;
        dst = &g_vT[((size_t)b * NPIX + ng) * NC + cb];
    }
#pragma unroll
    for (int q = 0; q < 4; q++) ((uint4*)dst)[q] = ((uint4*)tmp)[q];
}

// ---------------- flash attention: 64 queries x 128 channels per CTA, 2 CTAs/SM ----------------
#define CK   64                        // keys per chunk
#define CCH  128                       // channels per CTA
#define VSTR 136                       // smem halves per V row (128 + 8 pad)
#define KTILE_B (CK * 40 * 2)          // 5120
#define VTILE_B (CK * VSTR * 2)        // 17408
#define OFF_Q 0
#define OFF_K 5120                     // 2 buffers
#define OFF_V (OFF_K + 2 * KTILE_B)    // 15360, 2 buffers
#define SMEM_TOTAL (OFF_V + 2 * VTILE_B)  // 50176
#define ONES_H2 0x3C003C00u

__device__ __forceinline__ void flash_load_chunk(char* smem_raw, int buf, int b, int j0,
                                                 int ch0, int tid) {
    __half* k_s = (__half*)(smem_raw + OFF_K + buf * KTILE_B);
    __half* v_s = (__half*)(smem_raw + OFF_V + buf * VTILE_B);
    {   // K chunk 64x32
        int e = tid * 8;
        int r = e >> 5, c = e & 31;
        cp_async16(smem_u32(&k_s[r * 40 + c]),
                   &g_kT[((size_t)b * NPIX + j0 + r) * 32 + c]);
    }
#pragma unroll
    for (int p = 0; p < 4; p++) {  // V chunk 64x128
        int e = (tid + p * 256) * 8;
        int r = e >> 7, c = e & 127;
        cp_async16(smem_u32(&v_s[r * VSTR + c]),
                   &g_vT[((size_t)b * NPIX + j0 + r) * NC + ch0 + c]);
    }
}

__global__ __launch_bounds__(256, 2) void flash_kernel(float* __restrict__ out) {
    extern __shared__ char smem_raw[];
    __half* q_s = (__half*)(smem_raw + OFF_Q);

    int nq0 = blockIdx.x * 64;
    int b   = blockIdx.y;
    int ch0 = blockIdx.z * CCH;
    int tid = threadIdx.x;
    int w = tid >> 5, lane = tid & 31, g = lane >> 2, t4 = lane & 3;
    int mw = w & 3;       // query row group: rows [16*mw, 16*mw+16)
    int nh = w >> 2;      // channel quarter for PV: chans ch0 + [64*nh, +64)

    {   // load Q tile (64x32)
        int e = tid * 8;
        int r = e >> 5, c = e & 31;
        *(uint4*)&q_s[r * 40 + c] = *(const uint4*)&g_qT[((size_t)b * NPIX + nq0 + r) * 32 + c];
    }

    // prefetch chunk 0
    flash_load_chunk(smem_raw, 0, b, 0, ch0, tid);
    cp_commit();

    float acc[8][4];
#pragma unroll
    for (int i = 0; i < 8; i++)
#pragma unroll
        for (int j = 0; j < 4; j++) acc[i][j] = 0.f;
    float lacc[4] = {0.f, 0.f, 0.f, 0.f};
    float m0 = -1e30f, m1 = -1e30f;

    __syncthreads();  // Q visible
    // Q fragments (constant across key chunks)
    uint32_t qa[2][4];
#pragma unroll
    for (int ks = 0; ks < 2; ks++) {
        int row = 16 * mw + (lane & 15);
        int col = 16 * ks + ((lane >= 16) ? 8 : 0);
        ldm_x4(qa[ks], smem_u32(&q_s[row * 40 + col]));
    }

    const int NCHUNK = NPIX / CK;  // 64
#pragma unroll 1
    for (int kc = 0; kc < NCHUNK; kc++) {
        int buf = kc & 1;
        cp_wait<0>();
        __syncthreads();  // chunk kc visible; all warps done reading buf^1
        if (kc + 1 < NCHUNK) {
            flash_load_chunk(smem_raw, buf ^ 1, b, (kc + 1) * CK, ch0, tid);
            cp_commit();
        }

        __half* k_s = (__half*)(smem_raw + OFF_K + buf * KTILE_B);
        __half* v_s = (__half*)(smem_raw + OFF_V + buf * VTILE_B);

        // ---- S' = Q' K^T (log2 domain): 16 rows x 64 keys, in registers ----
        float sacc[8][4];
#pragma unroll
        for (int i = 0; i < 8; i++)
#pragma unroll
            for (int j = 0; j < 4; j++) sacc[i][j] = 0.f;
#pragma unroll
        for (int ks = 0; ks < 2; ks++) {
#pragma unroll
            for (int nbp = 0; nbp < 4; nbp++) {
                uint32_t bf[4];
                int key = nbp * 16 + (lane & 7) + ((lane >= 16) ? 8 : 0);
                int col = 16 * ks + ((lane & 8) ? 8 : 0);
                ldm_x4(bf, smem_u32(&k_s[key * 40 + col]));
                mma_16816(sacc[2 * nbp],     qa[ks], bf[0], bf[1]);
                mma_16816(sacc[2 * nbp + 1], qa[ks], bf[2], bf[3]);
            }
        }

        // ---- online softmax (base-2, fp16 exp) ----
        float mx0 = sacc[0][0], mx1 = sacc[0][2];
#pragma unroll
        for (int j = 0; j < 8; j++) {
            mx0 = fmaxf(mx0, fmaxf(sacc[j][0], sacc[j][1]));
            mx1 = fmaxf(mx1, fmaxf(sacc[j][2], sacc[j][3]));
        }
#pragma unroll
        for (int off = 1; off < 4; off <<= 1) {
            mx0 = fmaxf(mx0, __shfl_xor_sync(0xffffffffu, mx0, off));
            mx1 = fmaxf(mx1, __shfl_xor_sync(0xffffffffu, mx1, off));
        }
        float mn0 = fmaxf(m0, mx0), mn1 = fmaxf(m1, mx1);
        float al0 = ex2f(m0 - mn0), al1 = ex2f(m1 - mn1);
        m0 = mn0; m1 = mn1;

        // exp via f16x2 ex2 — output IS the packed P fragment
        uint32_t pa[4][4];
#pragma unroll
        for (int ks = 0; ks < 4; ks++) {
            pa[ks][0] = h2exp2(h2_as_u32(__floats2half2_rn(sacc[2 * ks][0] - mn0,     sacc[2 * ks][1] - mn0)));
            pa[ks][1] = h2exp2(h2_as_u32(__floats2half2_rn(sacc[2 * ks][2] - mn1,     sacc[2 * ks][3] - mn1)));
            pa[ks][2] = h2exp2(h2_as_u32(__floats2half2_rn(sacc[2 * ks + 1][0] - mn0, sacc[2 * ks + 1][1] - mn0)));
            pa[ks][3] = h2exp2(h2_as_u32(__floats2half2_rn(sacc[2 * ks + 1][2] - mn1, sacc[2 * ks + 1][3] - mn1)));
        }

        // rescale O accumulators and l accumulators
#pragma unroll
        for (int nt = 0; nt < 8; nt++) {
            acc[nt][0] *= al0; acc[nt][1] *= al0;
            acc[nt][2] *= al1; acc[nt][3] *= al1;
        }
        lacc[0] *= al0; lacc[1] *= al0; lacc[2] *= al1; lacc[3] *= al1;

        // ---- O += P V : 16 rows x 64 channels ----
#pragma unroll
        for (int ks = 0; ks < 4; ks++) {
#pragma unroll
            for (int nbp = 0; nbp < 4; nbp++) {
                uint32_t bf[4];
                int key  = 16 * ks + (lane & 15);
                int chan = nh * 64 + 16 * nbp + ((lane >= 16) ? 8 : 0);
                ldm_x4_t(bf, smem_u32(&v_s[key * VSTR + chan]));
                mma_16816(acc[2 * nbp],     pa[ks], bf[0], bf[1]);
                mma_16816(acc[2 * nbp + 1], pa[ks], bf[2], bf[3]);
            }
        }
        // ---- l += P . 1 (row sums via tensor core) ----
#pragma unroll
        for (int ks = 0; ks < 4; ks++)
            mma_16816(lacc, pa[ks], ONES_H2, ONES_H2);
    }

    float l0 = lacc[0], l1 = lacc[2];

    // ---- finalize: divide by l, stage transposed, coalesced write ----
    __syncthreads();
    float* o_s = (float*)smem_raw;  // [64][132] float = 33792 B, reuses buffers
    {
        int ra = 16 * mw + g;
        float inv0 = 1.f / l0;
        float inv1 = 1.f / l1;
#pragma unroll
        for (int nt = 0; nt < 8; nt++) {
            int col = nh * 64 + 8 * nt + 2 * t4;
            o_s[ra * 132 + col]           = acc[nt][0] * inv0;
            o_s[ra * 132 + col + 1]       = acc[nt][1] * inv0;
            o_s[(ra + 8) * 132 + col]     = acc[nt][2] * inv1;
            o_s[(ra + 8) * 132 + col + 1] = acc[nt][3] * inv1;
        }
    }
    __syncthreads();
    int nl = tid & 63;
    int cb = tid >> 6;  // 0..3
#pragma unroll
    for (int it = 0; it < 32; it++) {
        int c = it * 4 + cb;
        out[((size_t)b * NC + ch0 + c) * NPIX + nq0 + nl] = o_s[nl * 132 + c];
    }
}

// ---------------- launcher ----------------
extern "C" void kernel_launch(void* const* d_in, const int* in_sizes, int n_in,
                              void* d_out, int out_size) {
    (void)in_sizes; (void)n_in; (void)out_size;
    const float* x  = (const float*)d_in[0];
    const float* wq = (const float*)d_in[1];
    const float* bq = (const float*)d_in[2];
    const float* wk = (const float*)d_in[3];
    const float* bk = (const float*)d_in[4];
    const float* wv = (const float*)d_in[5];
    const float* bv = (const float*)d_in[6];
    float* out = (float*)d_out;

    pack_w_kernel<<<(MR * NC + 255) / 256, 256>>>(wq, wk, wv);
    pack_x_kernel<<<(NB * NC * NPIX / 4 + 255) / 256, 256>>>(x);

    dim3 pg(NPIX / 64, MR / 64, NB);
    proj_kernel<<<pg, 128>>>(bq, bk, bv);

    cudaFuncSetAttribute(flash_kernel, cudaFuncAttributeMaxDynamicSharedMemorySize, SMEM_TOTAL);
    dim3 fg(NPIX / 64, NB, NC / CCH);
    flash_kernel<<<fg, 256, SMEM_TOTAL>>>(out);
}